// round 1
// baseline (speedup 1.0000x reference)
#include <cuda_runtime.h>
#include <cuda_bf16.h>

// EdgeEncoding: out[h,i,j] = sum_e coeff[e] * enc[node[e], h] over entries with
// pair_idx[e] == i*N+j, enc = edge_attr @ W.T + b.
// Factorized: out[h,p] = g[p] . W[h] + b[h] * s[p], with
//   g[p] = sum_e c_e * edge_attr[node_e],  s[p] = sum_e c_e.
// pair_idx is sorted (emitted i-major, j-minor); padding tail has coeff==0.

#define NNODES 768
#define NN (NNODES * NNODES)   // 589824 pairs
#define NH 32

#define BT 256                  // threads per block, pass 1
#define ITEMS 24                // entries per thread
#define TILE (BT * ITEMS)       // 6144 entries per block
#define STRIDE (ITEMS + 1)      // padded smem stride (25, coprime with 32)

// Scratch (device globals; no allocation allowed)
__device__ float4 d_g[NN];
__device__ __align__(16) float d_s[NN];

// ---------------------------------------------------------------------------
// Kernel 0: zero the g/s accumulators (11.8 MB)
// ---------------------------------------------------------------------------
__global__ void zero_kernel() {
    int i = blockIdx.x * blockDim.x + threadIdx.x;
    float4 z = make_float4(0.f, 0.f, 0.f, 0.f);
    if (i < NN) {
        d_g[i] = z;
    } else {
        int j = i - NN;
        if (j < NN / 4) reinterpret_cast<float4*>(d_s)[j] = z;
    }
}

// ---------------------------------------------------------------------------
// Kernel 1: segmented reduction over the sorted COO stream.
// Each thread scans ITEMS consecutive entries (staged in padded smem for
// conflict-free access). Interior segments -> plain STG (exclusive by
// sortedness); segments touching a chunk boundary with matching neighbor key
// -> atomicAdd. Padding (coeff==0) segments are never flushed (as == 0).
// ---------------------------------------------------------------------------
__global__ void __launch_bounds__(BT) pass1_kernel(
    const int*   __restrict__ pair_idx,
    const int*   __restrict__ node_idx,
    const float* __restrict__ coeff,
    const float* __restrict__ edge_attr,   // [768,4] row-major
    int M)
{
    extern __shared__ char smem_raw[];
    int*    sp  = reinterpret_cast<int*>(smem_raw);          // BT*STRIDE ints
    int*    sn  = sp + BT * STRIDE;                          // BT*STRIDE ints
    float*  sc  = reinterpret_cast<float*>(sn + BT * STRIDE);// BT*STRIDE floats
    float4* sea = reinterpret_cast<float4*>(sc + BT * STRIDE); // 768 float4

    const int tid   = threadIdx.x;
    const int tile0 = blockIdx.x * TILE;

    // Stage edge_attr table (12 KB)
    for (int i = tid; i < NNODES; i += BT)
        sea[i] = reinterpret_cast<const float4*>(edge_attr)[i];

    // Stage tile: coalesced int4/float4 loads, scatter to padded layout
    for (int j = tid; j < TILE / 4; j += BT) {
        int i4  = j * 4;
        int ge  = tile0 + i4;
        int pos = (i4 / ITEMS) * STRIDE + (i4 % ITEMS);  // i4%24 in {0..20}: no group crossing
        if (ge + 3 < M) {
            int4   pv = reinterpret_cast<const int4*>(pair_idx)[ge >> 2];
            int4   nv = reinterpret_cast<const int4*>(node_idx)[ge >> 2];
            float4 cv = reinterpret_cast<const float4*>(coeff)[ge >> 2];
            sp[pos + 0] = pv.x; sp[pos + 1] = pv.y; sp[pos + 2] = pv.z; sp[pos + 3] = pv.w;
            sn[pos + 0] = nv.x; sn[pos + 1] = nv.y; sn[pos + 2] = nv.z; sn[pos + 3] = nv.w;
            sc[pos + 0] = cv.x; sc[pos + 1] = cv.y; sc[pos + 2] = cv.z; sc[pos + 3] = cv.w;
        } else {
            #pragma unroll
            for (int k = 0; k < 4; k++) {
                int g = ge + k;
                bool ok = (g < M);
                sp[pos + k] = ok ? pair_idx[g] : -1;
                sn[pos + k] = ok ? node_idx[g] : 0;
                sc[pos + k] = ok ? coeff[g]    : 0.f;
            }
        }
    }
    __syncthreads();

    const int*   spp = sp + tid * STRIDE;  // bank-conflict-free (stride 25)
    const int*   snn = sn + tid * STRIDE;
    const float* scc = sc + tid * STRIDE;

    // Neighbor keys to decide exclusive vs shared segments
    int prevk = (tid > 0)      ? sp[(tid - 1) * STRIDE + (ITEMS - 1)]
                               : (tile0 > 0 ? pair_idx[tile0 - 1] : -3);
    int nextk = (tid < BT - 1) ? sp[(tid + 1) * STRIDE]
                               : ((tile0 + TILE) < M ? pair_idx[tile0 + TILE] : -3);

    int   cur = spp[0];
    float ax = 0.f, ay = 0.f, az = 0.f, aw = 0.f, as = 0.f;
    bool  atStart = true;

    for (int k = 0; k < ITEMS; k++) {
        int key = spp[k];
        if (key != cur) {
            // flush (mid or head segment: right side is closed)
            if (cur >= 0 && as != 0.f) {
                bool shared_seg = atStart && (prevk == cur);
                float* gp = reinterpret_cast<float*>(&d_g[cur]);
                if (shared_seg) {
                    atomicAdd(gp + 0, ax); atomicAdd(gp + 1, ay);
                    atomicAdd(gp + 2, az); atomicAdd(gp + 3, aw);
                    atomicAdd(&d_s[cur], as);
                } else {
                    d_g[cur] = make_float4(ax, ay, az, aw);
                    d_s[cur] = as;
                }
            }
            cur = key; ax = ay = az = aw = as = 0.f; atStart = false;
        }
        float  c  = scc[k];
        float4 ea = sea[snn[k]];
        ax = fmaf(c, ea.x, ax);
        ay = fmaf(c, ea.y, ay);
        az = fmaf(c, ea.z, az);
        aw = fmaf(c, ea.w, aw);
        as += c;
    }
    // final flush: right side may be open
    if (cur >= 0 && as != 0.f) {
        bool shared_seg = (atStart && (prevk == cur)) || (nextk == cur);
        float* gp = reinterpret_cast<float*>(&d_g[cur]);
        if (shared_seg) {
            atomicAdd(gp + 0, ax); atomicAdd(gp + 1, ay);
            atomicAdd(gp + 2, az); atomicAdd(gp + 3, aw);
            atomicAdd(&d_s[cur], as);
        } else {
            d_g[cur] = make_float4(ax, ay, az, aw);
            d_s[cur] = as;
        }
    }
}

// ---------------------------------------------------------------------------
// Kernel 2: expand g/s -> 32 channels. Plane-major coalesced float4 stores.
// ---------------------------------------------------------------------------
#define BT2 256
#define PP  4   // pairs per thread

__global__ void __launch_bounds__(BT2) pass2_kernel(
    const float* __restrict__ W,   // [32,4]
    const float* __restrict__ b,   // [32]
    float* __restrict__ out)       // [32, 768*768]
{
    __shared__ float sW[NH * 4];
    __shared__ float sb[NH];
    int tid = threadIdx.x;
    if (tid < NH * 4) sW[tid] = W[tid];
    if (tid < NH)     sb[tid] = b[tid];
    __syncthreads();

    int p = (blockIdx.x * BT2 + tid) * PP;
    float4 g0 = d_g[p + 0];
    float4 g1 = d_g[p + 1];
    float4 g2 = d_g[p + 2];
    float4 g3 = d_g[p + 3];
    float4 sv = reinterpret_cast<const float4*>(d_s)[p >> 2];

    #pragma unroll 4
    for (int h = 0; h < NH; h++) {
        float w0 = sW[4 * h + 0], w1 = sW[4 * h + 1];
        float w2 = sW[4 * h + 2], w3 = sW[4 * h + 3];
        float bh = sb[h];
        float4 r;
        r.x = fmaf(g0.x, w0, fmaf(g0.y, w1, fmaf(g0.z, w2, fmaf(g0.w, w3, sv.x * bh))));
        r.y = fmaf(g1.x, w0, fmaf(g1.y, w1, fmaf(g1.z, w2, fmaf(g1.w, w3, sv.y * bh))));
        r.z = fmaf(g2.x, w0, fmaf(g2.y, w1, fmaf(g2.z, w2, fmaf(g2.w, w3, sv.z * bh))));
        r.w = fmaf(g3.x, w0, fmaf(g3.y, w1, fmaf(g3.z, w2, fmaf(g3.w, w3, sv.w * bh))));
        reinterpret_cast<float4*>(out)[(h * NN + p) >> 2] = r;
    }
}

// ---------------------------------------------------------------------------
// kernel_launch
// ---------------------------------------------------------------------------
extern "C" void kernel_launch(void* const* d_in, const int* in_sizes, int n_in,
                              void* d_out, int out_size)
{
    const float* edge_attr = nullptr;
    const float* W = nullptr;
    const float* b = nullptr;
    const int*   pair = nullptr;
    const int*   node = nullptr;
    const float* coeff = nullptr;
    int M = 0;
    int bigSeen = 0;

    // Bind inputs by element count (robust to exact ordering):
    //   3072 -> edge_attr, 128 -> W, 32 -> b,
    //   the three ~10M arrays in declaration order -> pair_idx, node_idx, coeff
    for (int i = 0; i < n_in; i++) {
        int s = in_sizes[i];
        if (s == NNODES * 4)      edge_attr = (const float*)d_in[i];
        else if (s == NH * 4)     W = (const float*)d_in[i];
        else if (s == NH)         b = (const float*)d_in[i];
        else if (s >= 1000000) {
            if (bigSeen == 0)      pair  = (const int*)d_in[i];
            else if (bigSeen == 1) node  = (const int*)d_in[i];
            else if (bigSeen == 2) { coeff = (const float*)d_in[i]; M = s; }
            bigSeen++;
        }
    }

    const size_t smemBytes = (size_t)BT * STRIDE * 4 * 2   // sp, sn
                           + (size_t)BT * STRIDE * 4       // sc
                           + (size_t)NNODES * 16;          // sea  => 89,088 B
    cudaFuncSetAttribute(pass1_kernel,
                         cudaFuncAttributeMaxDynamicSharedMemorySize,
                         (int)smemBytes);

    int zgrid = (NN + NN / 4 + 255) / 256;   // 2880
    zero_kernel<<<zgrid, 256>>>();

    int grid1 = (M + TILE - 1) / TILE;       // ~1628
    pass1_kernel<<<grid1, BT, smemBytes>>>(pair, node, coeff, edge_attr, M);

    int grid2 = NN / (BT2 * PP);             // 576
    pass2_kernel<<<grid2, BT2>>>(W, b, (float*)d_out);
}

// round 2
// speedup vs baseline: 1.3600x; 1.3600x over previous
#include <cuda_runtime.h>
#include <cuda_bf16.h>

// EdgeEncoding: out[h,i,j] = sum_e coeff[e] * enc[node[e], h], enc = edge_attr@W.T + b.
// Factorized: out[h,p] = g[p].W[h] + b[h]*s[p];  g[p]=sum c_e*edge_attr[node_e], s[p]=sum c_e.
// pair_idx is sorted over the real prefix; padding tail has coeff==0 (never flushed).

#define NNODES 768
#define NN (NNODES * NNODES)   // 589824 pairs
#define NH 32

#define BT 256                  // threads per block, pass 1
#define ITEMS 20                // entries per thread
#define TILE (BT * ITEMS)       // 5120 entries per block
#define STRIDE (ITEMS + 1)      // 21, coprime with 32 -> conflict-free per-thread scan

__device__ float4 d_g[NN];
__device__ __align__(16) float d_s[NN];

// ---------------------------------------------------------------------------
// Kernel 0: zero g/s (11.8 MB). 4 float4 per thread over a flat index space.
// ---------------------------------------------------------------------------
#define ZV 4
__global__ void zero_kernel() {
    int base = (blockIdx.x * blockDim.x + threadIdx.x) * ZV;
    float4 z = make_float4(0.f, 0.f, 0.f, 0.f);
    #pragma unroll
    for (int k = 0; k < ZV; k++) {
        int i = base + k;
        if (i < NN) d_g[i] = z;
        else {
            int j = i - NN;
            if (j < NN / 4) reinterpret_cast<float4*>(d_s)[j] = z;
        }
    }
}

// Branchless predicated flush: no BSSY/BSYNC, just 2 predicated STG.
__device__ __forceinline__ void pred_flush(int doit, int key,
                                           float ax, float ay, float az, float aw, float as)
{
    unsigned long long ga = (unsigned long long)(d_g + key);
    unsigned long long sa = (unsigned long long)(d_s + key);
    asm volatile(
        "{\n\t.reg .pred p;\n\t"
        "setp.ne.s32 p, %0, 0;\n\t"
        "@p st.global.v4.f32 [%1], {%3, %4, %5, %6};\n\t"
        "@p st.global.f32 [%2], %7;\n\t}"
        :: "r"(doit), "l"(ga), "l"(sa),
           "f"(ax), "f"(ay), "f"(az), "f"(aw), "f"(as));
}

__device__ __forceinline__ void flush_maybe_shared(bool shared_seg, int key,
                                                   float ax, float ay, float az,
                                                   float aw, float as)
{
    float* gp = reinterpret_cast<float*>(&d_g[key]);
    if (shared_seg) {
        atomicAdd(gp + 0, ax); atomicAdd(gp + 1, ay);
        atomicAdd(gp + 2, az); atomicAdd(gp + 3, aw);
        atomicAdd(&d_s[key], as);
    } else {
        d_g[key] = make_float4(ax, ay, az, aw);
        d_s[key] = as;
    }
}

// ---------------------------------------------------------------------------
// Kernel 1: segmented reduction over the sorted COO stream.
// ---------------------------------------------------------------------------
__global__ void __launch_bounds__(BT) pass1_kernel(
    const int*   __restrict__ pair_idx,
    const int*   __restrict__ node_idx,
    const float* __restrict__ coeff,
    const float* __restrict__ edge_attr,   // [768,4]
    int M)
{
    const int tile0 = blockIdx.x * TILE;

    // Padding early-exit: real coeffs are strictly positive and form a prefix.
    if (tile0 > 0 && __ldg(&coeff[tile0]) == 0.f) return;

    extern __shared__ char smem_raw[];
    int*    sp  = reinterpret_cast<int*>(smem_raw);            // BT*STRIDE
    int*    sn  = sp + BT * STRIDE;
    float*  sc  = reinterpret_cast<float*>(sn + BT * STRIDE);
    float4* sea = reinterpret_cast<float4*>(sc + BT * STRIDE); // 768 float4

    const int tid = threadIdx.x;

    for (int i = tid; i < NNODES; i += BT)
        sea[i] = reinterpret_cast<const float4*>(edge_attr)[i];

    // Stage tile: coalesced vec4 loads, scatter to padded per-thread layout.
    #pragma unroll
    for (int it = 0; it < TILE / 4 / BT; it++) {
        int j   = tid + it * BT;
        int i4  = j * 4;
        int ge  = tile0 + i4;
        int pos = (i4 / ITEMS) * STRIDE + (i4 % ITEMS);  // i4%20 in {0,4,8,12,16}
        if (ge + 3 < M) {
            int4   pv = reinterpret_cast<const int4*>(pair_idx)[ge >> 2];
            int4   nv = reinterpret_cast<const int4*>(node_idx)[ge >> 2];
            float4 cv = reinterpret_cast<const float4*>(coeff)[ge >> 2];
            sp[pos + 0] = pv.x; sp[pos + 1] = pv.y; sp[pos + 2] = pv.z; sp[pos + 3] = pv.w;
            sn[pos + 0] = nv.x; sn[pos + 1] = nv.y; sn[pos + 2] = nv.z; sn[pos + 3] = nv.w;
            sc[pos + 0] = cv.x; sc[pos + 1] = cv.y; sc[pos + 2] = cv.z; sc[pos + 3] = cv.w;
        } else {
            #pragma unroll
            for (int k = 0; k < 4; k++) {
                int g = ge + k;
                bool ok = (g < M);
                sp[pos + k] = ok ? pair_idx[g] : -1;
                sn[pos + k] = ok ? node_idx[g] : 0;
                sc[pos + k] = ok ? coeff[g]    : 0.f;
            }
        }
    }
    __syncthreads();

    const int*   spp = sp + tid * STRIDE;
    const int*   snn = sn + tid * STRIDE;
    const float* scc = sc + tid * STRIDE;

    int prevk = (tid > 0)      ? sp[(tid - 1) * STRIDE + (ITEMS - 1)]
                               : (tile0 > 0 ? __ldg(&pair_idx[tile0 - 1]) : -3);
    int nextk = (tid < BT - 1) ? sp[(tid + 1) * STRIDE]
                               : ((tile0 + TILE) < M ? __ldg(&pair_idx[tile0 + TILE]) : -3);

    int   cur = spp[0];
    float ax = 0.f, ay = 0.f, az = 0.f, aw = 0.f, as = 0.f;
    int   segidx = 0;
    int   s0key = 0;
    float s0x = 0.f, s0y = 0.f, s0z = 0.f, s0w = 0.f, s0s = 0.f;

    #pragma unroll
    for (int k = 0; k < ITEMS; k++) {
        int  key = spp[k];
        bool neq = (key != cur);

        // Interior segment flush (segidx>0): provably exclusive -> predicated stores.
        int doflush = (int)(neq & (segidx != 0) & (as != 0.f));
        pred_flush(doflush, cur, ax, ay, az, aw, as);

        // Stash segment 0 (may be shared with previous chunk) -> selp, no branch.
        bool stash = neq & (segidx == 0);
        s0key = stash ? cur : s0key;
        s0x = stash ? ax : s0x;  s0y = stash ? ay : s0y;
        s0z = stash ? az : s0z;  s0w = stash ? aw : s0w;
        s0s = stash ? as : s0s;

        segidx += (int)neq;

        float  c  = scc[k];
        float4 ea = sea[snn[k]];
        ax = fmaf(c, ea.x, neq ? 0.f : ax);
        ay = fmaf(c, ea.y, neq ? 0.f : ay);
        az = fmaf(c, ea.z, neq ? 0.f : az);
        aw = fmaf(c, ea.w, neq ? 0.f : aw);
        as = c + (neq ? 0.f : as);
        cur = key;
    }

    // Last (open) segment: may be shared with next chunk; if it's also the
    // only segment, may be shared with the previous chunk too.
    if (as != 0.f && cur >= 0) {
        bool shared_seg = (nextk == cur) || (segidx == 0 && prevk == cur);
        flush_maybe_shared(shared_seg, cur, ax, ay, az, aw, as);
    }
    // Stashed segment 0 (closed on the right inside this chunk).
    if (segidx > 0 && s0s != 0.f) {
        flush_maybe_shared(prevk == s0key, s0key, s0x, s0y, s0z, s0w, s0s);
    }
}

// ---------------------------------------------------------------------------
// Kernel 2: expand g/s -> 32 channels, plane-major coalesced float4 stores.
// ---------------------------------------------------------------------------
#define BT2 256
#define PP  4

__global__ void __launch_bounds__(BT2) pass2_kernel(
    const float* __restrict__ W,   // [32,4]
    const float* __restrict__ b,   // [32]
    float* __restrict__ out)       // [32, 768*768]
{
    __shared__ float sW[NH * 4];
    __shared__ float sb[NH];
    int tid = threadIdx.x;
    if (tid < NH * 4) sW[tid] = W[tid];
    if (tid < NH)     sb[tid] = b[tid];
    __syncthreads();

    int p = (blockIdx.x * BT2 + tid) * PP;
    float4 g0 = d_g[p + 0];
    float4 g1 = d_g[p + 1];
    float4 g2 = d_g[p + 2];
    float4 g3 = d_g[p + 3];
    float4 sv = reinterpret_cast<const float4*>(d_s)[p >> 2];

    #pragma unroll 4
    for (int h = 0; h < NH; h++) {
        float w0 = sW[4 * h + 0], w1 = sW[4 * h + 1];
        float w2 = sW[4 * h + 2], w3 = sW[4 * h + 3];
        float bh = sb[h];
        float4 r;
        r.x = fmaf(g0.x, w0, fmaf(g0.y, w1, fmaf(g0.z, w2, fmaf(g0.w, w3, sv.x * bh))));
        r.y = fmaf(g1.x, w0, fmaf(g1.y, w1, fmaf(g1.z, w2, fmaf(g1.w, w3, sv.y * bh))));
        r.z = fmaf(g2.x, w0, fmaf(g2.y, w1, fmaf(g2.z, w2, fmaf(g2.w, w3, sv.z * bh))));
        r.w = fmaf(g3.x, w0, fmaf(g3.y, w1, fmaf(g3.z, w2, fmaf(g3.w, w3, sv.w * bh))));
        reinterpret_cast<float4*>(out)[(h * NN + p) >> 2] = r;
    }
}

// ---------------------------------------------------------------------------
// kernel_launch
// ---------------------------------------------------------------------------
extern "C" void kernel_launch(void* const* d_in, const int* in_sizes, int n_in,
                              void* d_out, int out_size)
{
    const float* edge_attr = nullptr;
    const float* W = nullptr;
    const float* b = nullptr;
    const int*   pair = nullptr;
    const int*   node = nullptr;
    const float* coeff = nullptr;
    int M = 0;
    int bigSeen = 0;

    for (int i = 0; i < n_in; i++) {
        int s = in_sizes[i];
        if (s == NNODES * 4)      edge_attr = (const float*)d_in[i];
        else if (s == NH * 4)     W = (const float*)d_in[i];
        else if (s == NH)         b = (const float*)d_in[i];
        else if (s >= 1000000) {
            if (bigSeen == 0)      pair  = (const int*)d_in[i];
            else if (bigSeen == 1) node  = (const int*)d_in[i];
            else if (bigSeen == 2) { coeff = (const float*)d_in[i]; M = s; }
            bigSeen++;
        }
    }

    const size_t smemBytes = (size_t)BT * STRIDE * 4 * 3   // sp, sn, sc
                           + (size_t)NNODES * 16;          // sea => 76,800 B
    cudaFuncSetAttribute(pass1_kernel,
                         cudaFuncAttributeMaxDynamicSharedMemorySize,
                         (int)smemBytes);

    int ztot  = NN + NN / 4;                       // float4 slots
    int zgrid = (ztot + 256 * ZV - 1) / (256 * ZV);
    zero_kernel<<<zgrid, 256>>>();

    int grid1 = (M + TILE - 1) / TILE;
    pass1_kernel<<<grid1, BT, smemBytes>>>(pair, node, coeff, edge_attr, M);

    int grid2 = NN / (BT2 * PP);
    pass2_kernel<<<grid2, BT2>>>(W, b, (float*)d_out);
}